// round 12
// baseline (speedup 1.0000x reference)
#include <cuda_runtime.h>
#include <cstdint>

// HIRNN (GR4J-style) forward, R11: TWO rows per thread via packed f32x2
// (R10 fix: ptxas has fma.rn.f32x2 / mul.rn.f32x2 but NO min/max.f32x2 —
// min/max done as scalar FMNMX on the near-idle alu pipe; pairs held as
// float2 so mov.b64 pack/unpack elides to register-pair naming).
//
// Per packed step (2 row-steps): ~14 packed fma + 12 scalar mnmx + 2 MUFU.
// One packed dependent chain advances both rows -> per-row chain halves.
// 64 warps; ping-pong register double-buffered inputs (from R8/R9).
//
// Step identities (exact away from <=1e-6 heaviside ties):
//  - heaviside select pairs == min/max
//  - GW >= 0 by induction  =>  BAS = RecK*GW,  GW' = (1-RecK)*GW + RECn
//  - max(s-1,0) == s - min(s,1); min(s,1) feeds the u-clamp
//  - clip(+-1e5) provably inactive; state normalized u = SMS/SMSC in [0,1]
// Q[t] (t>=1) uses the pre-step state at t (in-loop); Q[0] uses the FINAL
// state (roll shift=1), recomputed after the loop.

using u64 = unsigned long long;

__device__ __forceinline__ float ex2f(float x) {
    float y;
    asm("ex2.approx.f32 %0, %1;" : "=f"(y) : "f"(x));
    return y;
}
__device__ __forceinline__ u64 pk(float2 v) {
    u64 r; asm("mov.b64 %0, {%1, %2};" : "=l"(r) : "f"(v.x), "f"(v.y)); return r;
}
__device__ __forceinline__ float2 upk(u64 v) {
    float2 r; asm("mov.b64 {%0, %1}, %2;" : "=f"(r.x), "=f"(r.y) : "l"(v)); return r;
}
__device__ __forceinline__ float2 fma2(float2 a, float2 b, float2 c) {
    u64 D;
    asm("fma.rn.f32x2 %0, %1, %2, %3;" : "=l"(D) : "l"(pk(a)), "l"(pk(b)), "l"(pk(c)));
    return upk(D);
}
__device__ __forceinline__ float2 mul2(float2 a, float2 b) {
    u64 D;
    asm("mul.rn.f32x2 %0, %1, %2;" : "=l"(D) : "l"(pk(a)), "l"(pk(b)));
    return upk(D);
}
__device__ __forceinline__ float2 min2(float2 a, float2 b) {
    return make_float2(fminf(a.x, b.x), fminf(a.y, b.y));
}
__device__ __forceinline__ float2 max2(float2 a, float2 b) {
    return make_float2(fmaxf(a.x, b.x), fmaxf(a.y, b.y));
}
__device__ __forceinline__ float2 bc2(float v) { return make_float2(v, v); }

struct P2 {
    float2 INSC2, nONE2, ck22, lC2, ten2, nivS2, one2, zero2,
           nSUB2, nCRbi2, ivS2, CRAK2, SMSC2, RecK2, SUB2, alpha2;
};

// One packed step (both rows): advances (u2, g2); returns packed Q from the
// PRE-step state.
__device__ __forceinline__ float2 stepq2(float2 Prec, float2 PET,
                                         float2& u2, float2& g2, const P2& p)
{
    float2 INTm = min2(PET, Prec);
    float2 INT  = min2(p.INSC2, INTm);
    float2 INR  = fma2(INT, p.nONE2, Prec);     // Prec - INT
    float2 POT  = fma2(INT, p.nONE2, PET);      // PET  - INT

    // critical chain: FFMA2 -> 2x MUFU -> 2x FMNMX -> FFMA2 -> clamp
    float2 arg = fma2(p.ck22, u2, p.lC2);
    float2 cap = make_float2(ex2f(arg.x), ex2f(arg.y));  // COEFF*exp(-SQ*u)
    float2 RMO = min2(cap, INR);

    // off-chain polynomials (overlap the MUFUs)
    float2 t10  = mul2(u2, p.ten2);
    float2 m    = min2(t10, POT);
    float2 base = fma2(p.nivS2, m, u2);         // u - ETS/SMSC
    float2 a    = fma2(p.nSUB2, u2, p.one2);    // 1 - SUB*u
    float2 bi   = fma2(p.nCRbi2, u2, p.ivS2);   // (1 - CRAK*u)/SMSC
    float2 fi   = mul2(a, bi);
    float2 w    = mul2(u2, RMO);

    float2 s    = fma2(RMO, fi, base);          // pre-clamp next u
    float2 umid = min2(s, p.one2);
    float2 un   = max2(umid, p.zero2);
    float2 ov   = fma2(umid, p.nONE2, s);       // == max(s-1,0)

    float2 cw   = mul2(p.CRAK2, w);
    float2 REC  = mul2(cw, a);
    float2 RECn = fma2(p.SMSC2, ov, REC);
    float2 dq   = fma2(RMO, p.nONE2, INR);      // INR - RMO
    float2 t1   = fma2(p.RecK2, g2, dq);        // IRUN + BAS
    float2 q    = fma2(p.SUB2, w, t1);          // + SRUN

    g2 = fma2(p.alpha2, g2, RECn);              // (1-RecK)*GW + RECn
    u2 = un;
    return q;
}

// 8 packed timesteps from register buffers, then 4x STG.128.
__device__ __forceinline__ void do8(const float4* bA, const float4* bB,
                                    float2& u2, float2& g2, const P2& p,
                                    float4* oA, float4* oB, int idx)
{
    float2 q[8];
    #pragma unroll
    for (int k = 0; k < 8; ++k) {
        float4 va = bA[k >> 1], vb = bB[k >> 1];
        float pa = (k & 1) ? va.z : va.x;
        float ea = (k & 1) ? va.w : va.y;
        float pb = (k & 1) ? vb.z : vb.x;
        float eb = (k & 1) ? vb.w : vb.y;
        q[k] = stepq2(make_float2(pa, pb), make_float2(ea, eb), u2, g2, p);
    }
    float4 qa0 = make_float4(q[0].x, q[1].x, q[2].x, q[3].x);
    float4 qa1 = make_float4(q[4].x, q[5].x, q[6].x, q[7].x);
    float4 qb0 = make_float4(q[0].y, q[1].y, q[2].y, q[3].y);
    float4 qb1 = make_float4(q[4].y, q[5].y, q[6].y, q[7].y);
    oA[idx * 2]     = qa0;
    oA[idx * 2 + 1] = qa1;
    oB[idx * 2]     = qb0;
    oB[idx * 2 + 1] = qb1;
}

template <int T>
__global__ __launch_bounds__(32, 1)
void hirnn_kernel(const float* __restrict__ in,
                  const float* __restrict__ pINSC,
                  const float* __restrict__ pCOEFF,
                  const float* __restrict__ pSQ,
                  const float* __restrict__ pSMSC,
                  const float* __restrict__ pSUB,
                  const float* __restrict__ pCRAK,
                  const float* __restrict__ pRecK,
                  float* __restrict__ out, int B)
{
    int half = B >> 1;
    int ba = blockIdx.x * 32 + threadIdx.x;
    if (ba >= half) return;
    int bb = ba + half;

    float INSC = fminf(fmaxf(pINSC[0]  * 5.f,   0.5f),   5.f);
    float CO   = fminf(fmaxf(pCOEFF[0] * 400.f, 50.f),   400.f);
    float SQ   = fminf(fmaxf(pSQ[0]    * 6.f,   0.f),    6.f);
    float SMSC = fminf(fmaxf(pSMSC[0]  * 500.f, 50.f),   500.f);
    float SUB  = fminf(fmaxf(pSUB[0],           0.f),    1.f);
    float CRAK = fminf(fmaxf(pCRAK[0],          0.f),    1.f);
    float RecK = fminf(fmaxf(pRecK[0]  * 0.3f,  0.003f), 0.3f);
    float ivS  = 1.f / SMSC;
    float ck2  = -SQ * 1.44269504088896340736f;  // -SQ*log2(e)
    float lC   = __log2f(CO);

    P2 p;
    p.INSC2  = bc2(INSC);
    p.nONE2  = bc2(-1.f);
    p.ck22   = bc2(ck2);
    p.lC2    = bc2(lC);
    p.ten2   = bc2(10.f);
    p.nivS2  = bc2(-ivS);
    p.one2   = bc2(1.f);
    p.zero2  = bc2(0.f);
    p.nSUB2  = bc2(-SUB);
    p.nCRbi2 = bc2(-CRAK * ivS);
    p.ivS2   = bc2(ivS);
    p.CRAK2  = bc2(CRAK);
    p.SMSC2  = bc2(SMSC);
    p.RecK2  = bc2(RecK);
    p.SUB2   = bc2(SUB);
    p.alpha2 = bc2(1.f - RecK);

    const float4* rowA = reinterpret_cast<const float4*>(in + (size_t)ba * T * 2);
    const float4* rowB = reinterpret_cast<const float4*>(in + (size_t)bb * T * 2);
    float4* oA = reinterpret_cast<float4*>(out + (size_t)ba * T);
    float4* oB = reinterpret_cast<float4*>(out + (size_t)bb * T);

    constexpr int NB = T / 8;   // bodies of 8 timesteps; 128 for T=1024 (even)

    float4 CA[4], CB[4], NA[4], NB_[4];
    #pragma unroll
    for (int j = 0; j < 4; ++j) { CA[j] = __ldg(&rowA[j]); CB[j] = __ldg(&rowB[j]); }

    float PrecA0 = CA[0].x, PETA0 = CA[0].y;
    float PrecB0 = CB[0].x, PETB0 = CB[0].y;

    float2 u2 = bc2(0.f);
    float2 g2 = bc2(0.f);

    for (int i = 0; i < NB; i += 2) {
        // prefetch body i+1 (always valid: NB even)
        #pragma unroll
        for (int j = 0; j < 4; ++j) {
            NA[j]  = __ldg(&rowA[(i + 1) * 4 + j]);
            NB_[j] = __ldg(&rowB[(i + 1) * 4 + j]);
        }
        do8(CA, CB, u2, g2, p, oA, oB, i);

        // prefetch body i+2 (last iter: dummy reload of body 0)
        int j2 = (i + 2 < NB) ? i + 2 : 0;
        #pragma unroll
        for (int j = 0; j < 4; ++j) {
            CA[j] = __ldg(&rowA[j2 * 4 + j]);
            CB[j] = __ldg(&rowB[j2 * 4 + j]);
        }
        do8(NA, NB_, u2, g2, p, oA, oB, i + 1);
    }

    // Q[0]: roll(shift=1) puts the FINAL state at t=0.
    float2 u2f = u2, g2f = g2;
    float2 q0 = stepq2(make_float2(PrecA0, PrecB0),
                       make_float2(PETA0, PETB0), u2f, g2f, p);
    out[(size_t)ba * T] = q0.x;
    out[(size_t)bb * T] = q0.y;
}

extern "C" void kernel_launch(void* const* d_in, const int* in_sizes, int n_in,
                              void* d_out, int out_size)
{
    const float* in    = (const float*)d_in[0];
    const float* INSC  = (const float*)d_in[1];
    const float* COEFF = (const float*)d_in[2];
    const float* SQ    = (const float*)d_in[3];
    const float* SMSC  = (const float*)d_in[4];
    const float* SUB   = (const float*)d_in[5];
    const float* CRAK  = (const float*)d_in[6];
    const float* RecK  = (const float*)d_in[7];
    float* out = (float*)d_out;

    constexpr int T = 1024;
    int B = out_size / T;
    int half = B >> 1;
    int blocks = (half + 31) / 32;
    hirnn_kernel<T><<<blocks, 32>>>(in, INSC, COEFF, SQ, SMSC, SUB, CRAK, RecK,
                                    out, B);
}

// round 13
// speedup vs baseline: 1.3434x; 1.3434x over previous
#include <cuda_runtime.h>
#include <cstdint>

// HIRNN (GR4J-style) forward, R13: R8 skeleton + chain surgery.
//  - max(u,0) clamp removed: s >= 0 provable (base >= 0.8u, RMO*fi >= 0).
//  - min hoisted through fma: fi >= 0  =>  s = min(cap*fi+base, INR*fi+base);
//    s_inr and min(s_inr,1) are computed OFF the loop-carried chain (inside
//    the MUFU shadow), leaving the chain as
//        FFMA(arg) -> MUFU.EX2 -> FFMA(s_cap) -> FMNMX(u')   (~31 cyc/step).
//    Bitwise identical to the previous min-then-fma form.
// 128 warps (1 row/thread), register double-buffered input prefetch (R8),
// __launch_bounds__(32,1) for full reg budget (R4 lesson).
//
// Step identities (exact away from <=1e-6 heaviside ties):
//  - heaviside select pairs == min/max
//  - GW >= 0 by induction  =>  BAS = RecK*GW,  GW' = (1-RecK)*GW + RECn
//  - ov = max(s-1,0) == s - min(s,1)
//  - clip(+-1e5) provably inactive; state normalized u = SMS/SMSC in [0,1]
// Q[t] (t>=1) uses the pre-step state at t (in-loop); Q[0] uses the FINAL
// state (roll shift=1), recomputed after the loop.

__device__ __forceinline__ float ex2f(float x) {
    float y;
    asm("ex2.approx.f32 %0, %1;" : "=f"(y) : "f"(x));
    return y;
}

struct Params {
    float INSC, SMSC, SUB, CRAK, RecK, alpha, ivS, ck2, lC, nSUB, nCRbi;
};

__device__ __forceinline__ float stepq(float Prec, float PET,
                                       float& u, float& GW, const Params& p)
{
    float INTm = fminf(PET, Prec);            // alu
    float INT  = fminf(p.INSC, INTm);         // alu
    float INR  = Prec - INT;                  // fma
    float POT  = PET - INT;                   // fma

    // ---- loop-carried chain ----
    float arg = fmaf(p.ck2, u, p.lC);         // fma   (needs u)
    float cap = ex2f(arg);                    // mufu : COEFF*exp(-SQ*u)

    // ---- off-chain, inside the MUFU shadow ----
    float t10   = u * 10.0f;                  // fma
    float m     = fminf(t10, POT);            // alu : ETS
    float base  = fmaf(-p.ivS, m, u);         // fma : u - ETS/SMSC  (>= 0)
    float a     = fmaf(p.nSUB,  u, 1.0f);     // fma : 1 - SUB*u
    float bi    = fmaf(p.nCRbi, u, p.ivS);    // fma : (1 - CRAK*u)/SMSC
    float fi    = a * bi;                     // fma  (>= 0)
    float s_inr = fmaf(INR, fi, base);        // fma : s if INR-limited
    float t2    = fminf(s_inr, 1.0f);         // alu

    // ---- chain tail ----
    float s_cap = fmaf(cap, fi, base);        // fma : s if cap-limited
    float u_n   = fminf(s_cap, t2);           // alu : next u = min(s,1), s>=0

    // ---- off-chain tail: recharge / groundwater / discharge ----
    float s    = fminf(s_cap, s_inr);         // alu : true pre-clamp s
    float ov   = s - u_n;                     // fma : == max(s-1,0)
    float RMO  = fminf(cap, INR);             // alu
    float w    = u * RMO;                     // fma
    float cw   = p.CRAK * w;                  // fma
    float REC  = cw * a;                      // fma
    float RECn = fmaf(p.SMSC, ov, REC);       // fma
    float dq   = INR - RMO;                   // fma
    float t1   = fmaf(p.RecK, GW, dq);        // fma : IRUN + BAS
    float q    = fmaf(p.SUB,  w,  t1);        // fma : + SRUN

    GW = fmaf(p.alpha, GW, RECn);             // fma : (1-RecK)*GW + RECn
    u  = u_n;
    return q;
}

template <int T>
__global__ __launch_bounds__(32, 1)
void hirnn_kernel(const float* __restrict__ in,
                  const float* __restrict__ pINSC,
                  const float* __restrict__ pCOEFF,
                  const float* __restrict__ pSQ,
                  const float* __restrict__ pSMSC,
                  const float* __restrict__ pSUB,
                  const float* __restrict__ pCRAK,
                  const float* __restrict__ pRecK,
                  float* __restrict__ out, int B)
{
    int bidx = blockIdx.x * 32 + threadIdx.x;
    if (bidx >= B) return;

    Params p;
    p.INSC   = fminf(fmaxf(pINSC[0]  * 5.f,   0.5f),   5.f);
    float CO = fminf(fmaxf(pCOEFF[0] * 400.f, 50.f),   400.f);
    float SQ = fminf(fmaxf(pSQ[0]    * 6.f,   0.f),    6.f);
    p.SMSC   = fminf(fmaxf(pSMSC[0]  * 500.f, 50.f),   500.f);
    p.SUB    = fminf(fmaxf(pSUB[0],           0.f),    1.f);
    p.CRAK   = fminf(fmaxf(pCRAK[0],          0.f),    1.f);
    p.RecK   = fminf(fmaxf(pRecK[0]  * 0.3f,  0.003f), 0.3f);
    p.alpha  = 1.f - p.RecK;
    p.ivS    = 1.f / p.SMSC;
    p.ck2    = -SQ * 1.44269504088896340736f;   // -SQ*log2(e)
    p.lC     = __log2f(CO);
    p.nSUB   = -p.SUB;
    p.nCRbi  = -p.CRAK * p.ivS;

    const float4* row  = reinterpret_cast<const float4*>(in + (size_t)bidx * T * 2);
    float4*       orow = reinterpret_cast<float4*>(out + (size_t)bidx * T);

    constexpr int NBODY = T / 16;   // 64 bodies of 16 timesteps

    float4 buf[8];
    #pragma unroll
    for (int j = 0; j < 8; ++j) buf[j] = __ldg(&row[j]);

    float Prec0 = buf[0].x, PET0 = buf[0].y;
    float u = 0.f, GW = 0.f;

    for (int i = 0; i < NBODY; ++i) {
        // prefetch next body (last iter: reload body 0, discarded)
        int nb = (i + 1 < NBODY) ? (i + 1) * 8 : 0;
        float4 nxt[8];
        #pragma unroll
        for (int j = 0; j < 8; ++j) nxt[j] = __ldg(&row[nb + j]);

        // compute 16 steps from buf
        #pragma unroll
        for (int k = 0; k < 4; ++k) {
            float4 q;
            q.x = stepq(buf[2*k].x,   buf[2*k].y,   u, GW, p);
            q.y = stepq(buf[2*k].z,   buf[2*k].w,   u, GW, p);
            q.z = stepq(buf[2*k+1].x, buf[2*k+1].y, u, GW, p);
            q.w = stepq(buf[2*k+1].z, buf[2*k+1].w, u, GW, p);
            orow[i * 4 + k] = q;   // q.x at i==0,k==0 is a placeholder
        }

        #pragma unroll
        for (int j = 0; j < 8; ++j) buf[j] = nxt[j];
    }

    // Q[0]: roll(shift=1) puts the FINAL state at t=0.
    float u2 = u, g2 = GW;
    out[(size_t)bidx * T] = stepq(Prec0, PET0, u2, g2, p);
}

extern "C" void kernel_launch(void* const* d_in, const int* in_sizes, int n_in,
                              void* d_out, int out_size)
{
    const float* in    = (const float*)d_in[0];
    const float* INSC  = (const float*)d_in[1];
    const float* COEFF = (const float*)d_in[2];
    const float* SQ    = (const float*)d_in[3];
    const float* SMSC  = (const float*)d_in[4];
    const float* SUB   = (const float*)d_in[5];
    const float* CRAK  = (const float*)d_in[6];
    const float* RecK  = (const float*)d_in[7];
    float* out = (float*)d_out;

    constexpr int T = 1024;
    int B = out_size / T;
    int blocks = (B + 31) / 32;
    hirnn_kernel<T><<<blocks, 32>>>(in, INSC, COEFF, SQ, SMSC, SUB, CRAK, RecK,
                                    out, B);
}